// round 3
// baseline (speedup 1.0000x reference)
#include <cuda_runtime.h>
#include <math.h>

// Problem constants
#define B_DIM 64
#define S_DIM 4096
#define D_DIM 256
#define LN_EPS 1e-3f

// Pass1 tiling: 8 warps/CTA, 32 rows/warp -> 256 rows per CTA
#define WPB 8
#define RPW 32
#define ROWS_PER_CTA (WPB * RPW)           // 256
#define CTAS_PER_B (S_DIM / ROWS_PER_CTA)  // 16
#define PARTIALS_PER_B (CTAS_PER_B * WPB)  // 128

// Pass2 split: 16 CTAs per batch, 8 partials each
#define SPLIT2 16
#define CHUNK2 (PARTIALS_PER_B / SPLIT2)   // 8

// Scratch. No max-tracking: scores are LN-bounded, exp() cannot overflow,
// so partials combine LINEARLY (sum of acc, sum of l).
__device__ float g_acc[B_DIM * PARTIALS_PER_B * D_DIM];   // 8 MB
__device__ float g_l[B_DIM * PARTIALS_PER_B];
__device__ float g_part[SPLIT2 * B_DIM * D_DIM];          // 1 MB

__device__ __forceinline__ float warp_sum(float v) {
#pragma unroll
    for (int off = 16; off > 0; off >>= 1)
        v += __shfl_xor_sync(0xffffffffu, v, off);
    return v;
}

// ---------------------------------------------------------------------------
// Pass 1: single pass over x. Each warp: 32 consecutive rows, 2 per iter.
// Unnormalized softmax accumulation: acc += exp(score)*x, l += exp(score).
// No running max -> no rescale chain, fewer registers, higher occupancy.
// ---------------------------------------------------------------------------
__global__ __launch_bounds__(WPB * 32, 5) void attn_pool_pass1(
    const float* __restrict__ x, const float* __restrict__ mask,
    const float* __restrict__ gamma, const float* __restrict__ beta,
    const float* __restrict__ w, const float* __restrict__ bias_p) {
    const int b = blockIdx.y;
    const int warp = threadIdx.x >> 5;
    const int lane = threadIdx.x & 31;
    const int d0 = lane * 8;

    // Per-lane gamma*w; warp-uniform constants GW, BW.
    float gw[8];
    float gwsum = 0.f, bwsum = 0.f;
#pragma unroll
    for (int i = 0; i < 8; i++) {
        float wi = w[d0 + i];
        gw[i] = gamma[d0 + i] * wi;
        gwsum += gw[i];
        bwsum += beta[d0 + i] * wi;
    }
    const float GW = warp_sum(gwsum);
    const float BW = warp_sum(bwsum) + bias_p[0];

    const int row0 = blockIdx.x * ROWS_PER_CTA + warp * RPW;
    const float* xb = x + ((size_t)b * S_DIM + row0) * D_DIM;
    const float* mb = mask + (size_t)b * S_DIM + row0;

    float l = 0.f;
    float acc[8];
#pragma unroll
    for (int i = 0; i < 8; i++) acc[i] = 0.f;

    for (int r = 0; r < RPW; r += 2) {
        // Two rows: 4 independent LDG.128 per lane, fully coalesced.
        const float* rp = xb + (size_t)r * D_DIM + d0;
        const float4 a0 = *reinterpret_cast<const float4*>(rp);
        const float4 a1 = *reinterpret_cast<const float4*>(rp + 4);
        const float4 b0 = *reinterpret_cast<const float4*>(rp + D_DIM);
        const float4 b1 = *reinterpret_cast<const float4*>(rp + D_DIM + 4);
        const float2 mk = *reinterpret_cast<const float2*>(mb + r);
        float xa[8] = {a0.x, a0.y, a0.z, a0.w, a1.x, a1.y, a1.z, a1.w};
        float xc[8] = {b0.x, b0.y, b0.z, b0.w, b1.x, b1.y, b1.z, b1.w};

        float sxA = 0.f, sxxA = 0.f, sdA = 0.f;
        float sxB = 0.f, sxxB = 0.f, sdB = 0.f;
#pragma unroll
        for (int i = 0; i < 8; i++) {
            sxA += xa[i];
            sxxA = fmaf(xa[i], xa[i], sxxA);
            sdA = fmaf(xa[i], gw[i], sdA);
            sxB += xc[i];
            sxxB = fmaf(xc[i], xc[i], sxxB);
            sdB = fmaf(xc[i], gw[i], sdB);
        }
        // Six interleaved warp reductions (independent chains).
#pragma unroll
        for (int off = 16; off > 0; off >>= 1) {
            sxA += __shfl_xor_sync(0xffffffffu, sxA, off);
            sxB += __shfl_xor_sync(0xffffffffu, sxB, off);
            sxxA += __shfl_xor_sync(0xffffffffu, sxxA, off);
            sxxB += __shfl_xor_sync(0xffffffffu, sxxB, off);
            sdA += __shfl_xor_sync(0xffffffffu, sdA, off);
            sdB += __shfl_xor_sync(0xffffffffu, sdB, off);
        }

        const float muA = sxA * (1.f / D_DIM);
        const float muB = sxB * (1.f / D_DIM);
        const float varA = sxxA * (1.f / D_DIM) - muA * muA;
        const float varB = sxxB * (1.f / D_DIM) - muB * muB;
        const float rsA = rsqrtf(varA + LN_EPS);
        const float rsB = rsqrtf(varB + LN_EPS);
        const float sA = rsA * (sdA - muA * GW) + BW + (1.f - mk.x) * -1e9f;
        const float sB = rsB * (sdB - muB * GW) + BW + (1.f - mk.y) * -1e9f;

        // Unnormalized accumulation (masked rows: exp(-1e9) -> 0).
        const float pA = __expf(sA);
        const float pB = __expf(sB);
        l += pA + pB;
#pragma unroll
        for (int i = 0; i < 8; i++)
            acc[i] = fmaf(pA, xa[i], fmaf(pB, xc[i], acc[i]));
    }

    // Write partial state.
    const int ip = blockIdx.x * WPB + warp;  // 0..127 within batch
    const size_t pbase = (size_t)b * PARTIALS_PER_B + ip;
    if (lane == 0) g_l[pbase] = l;
    float* ab = g_acc + pbase * D_DIM + d0;
    *reinterpret_cast<float4*>(ab) = make_float4(acc[0], acc[1], acc[2], acc[3]);
    *reinterpret_cast<float4*>(ab + 4) = make_float4(acc[4], acc[5], acc[6], acc[7]);
}

// ---------------------------------------------------------------------------
// Pass 2: grid (B, SPLIT2). Plain linear reduction of an 8-partial chunk
// over all 256 dims (coalesced across threads).
// ---------------------------------------------------------------------------
__global__ __launch_bounds__(256) void attn_pool_pass2() {
    const int b = blockIdx.x;
    const int split = blockIdx.y;
    const int t = threadIdx.x;

    const size_t pb = (size_t)b * PARTIALS_PER_B + (size_t)split * CHUNK2;
    const float* ab = g_acc + pb * D_DIM + t;
    float o = 0.f;
#pragma unroll
    for (int i = 0; i < CHUNK2; i++)
        o += ab[(size_t)i * D_DIM];
    g_part[((size_t)split * B_DIM + b) * D_DIM + t] = o;
}

// ---------------------------------------------------------------------------
// Pass 3: sum SPLIT2 split-partials + divide by total l. 64 CTAs.
// ---------------------------------------------------------------------------
__global__ __launch_bounds__(256) void attn_pool_pass3(float* __restrict__ out) {
    const int b = blockIdx.x;
    const int t = threadIdx.x;
    const int lane = t & 31;

    __shared__ float Lsh;
    if (t < 32) {
        // 128 l-values per batch: 4 per lane, then warp-reduce.
        const float* lp = g_l + (size_t)b * PARTIALS_PER_B;
        float s = lp[lane] + lp[lane + 32] + lp[lane + 64] + lp[lane + 96];
#pragma unroll
        for (int off = 16; off > 0; off >>= 1)
            s += __shfl_xor_sync(0xffffffffu, s, off);
        if (lane == 0) Lsh = s;
    }
    __syncthreads();
    const float Linv = 1.f / Lsh;

    float o = 0.f;
#pragma unroll
    for (int s = 0; s < SPLIT2; s++)
        o += g_part[((size_t)s * B_DIM + b) * D_DIM + t];
    out[(size_t)b * D_DIM + t] = o * Linv;
}

extern "C" void kernel_launch(void* const* d_in, const int* in_sizes, int n_in,
                              void* d_out, int out_size) {
    const float* x = (const float*)d_in[0];      // [64,4096,256]
    const float* mask = (const float*)d_in[1];   // [64,4096]
    const float* gamma = (const float*)d_in[2];  // [256]
    const float* beta = (const float*)d_in[3];   // [256]
    const float* w = (const float*)d_in[4];      // [256]
    const float* bias = (const float*)d_in[5];   // scalar
    float* out = (float*)d_out;                  // [64,256]

    dim3 grid1(CTAS_PER_B, B_DIM);
    attn_pool_pass1<<<grid1, WPB * 32>>>(x, mask, gamma, beta, w, bias);
    dim3 grid2(B_DIM, SPLIT2);
    attn_pool_pass2<<<grid2, 256>>>();
    attn_pool_pass3<<<B_DIM, 256>>>(out);
}

// round 5
// speedup vs baseline: 1.0285x; 1.0285x over previous
#include <cuda_runtime.h>
#include <math.h>

// Problem constants
#define B_DIM 64
#define S_DIM 4096
#define D_DIM 256
#define LN_EPS 1e-3f

// Pass1 tiling: 8 warps/CTA, 32 rows/warp -> 256 rows per CTA
#define WPB 8
#define RPW 32
#define ROWS_PER_CTA (WPB * RPW)           // 256
#define CTAS_PER_B (S_DIM / ROWS_PER_CTA)  // 16
#define PARTIALS_PER_B (CTAS_PER_B * WPB)  // 128

// Pass2 split: 16 CTAs per batch, 8 partials each
#define SPLIT2 16
#define CHUNK2 (PARTIALS_PER_B / SPLIT2)   // 8

// Scratch. No max-tracking: scores are LN-bounded, exp() cannot overflow,
// so partials combine LINEARLY (sum of acc, sum of l).
__device__ float g_acc[B_DIM * PARTIALS_PER_B * D_DIM];   // 8 MB
__device__ float g_l[B_DIM * PARTIALS_PER_B];
__device__ float g_part[SPLIT2 * B_DIM * D_DIM];          // 1 MB

__device__ __forceinline__ float warp_sum(float v) {
#pragma unroll
    for (int off = 16; off > 0; off >>= 1)
        v += __shfl_xor_sync(0xffffffffu, v, off);
    return v;
}

// ---------------------------------------------------------------------------
// Pass 1: single pass over x, software-pipelined. Each warp: 32 rows, 2 per
// iteration. The NEXT iteration's global loads are issued before the current
// iteration's shfl-reduce/exp/acc chain, so DRAM latency overlaps compute.
// ---------------------------------------------------------------------------
__global__ __launch_bounds__(WPB * 32) void attn_pool_pass1(
    const float* __restrict__ x, const float* __restrict__ mask,
    const float* __restrict__ gamma, const float* __restrict__ beta,
    const float* __restrict__ w, const float* __restrict__ bias_p) {
    const int b = blockIdx.y;
    const int warp = threadIdx.x >> 5;
    const int lane = threadIdx.x & 31;
    const int d0 = lane * 8;

    // Per-lane gamma*w; warp-uniform constants GW, BW.
    float gw[8];
    float gwsum = 0.f, bwsum = 0.f;
#pragma unroll
    for (int i = 0; i < 8; i++) {
        float wi = w[d0 + i];
        gw[i] = gamma[d0 + i] * wi;
        gwsum += gw[i];
        bwsum += beta[d0 + i] * wi;
    }
    const float GW = warp_sum(gwsum);
    const float BW = warp_sum(bwsum) + bias_p[0];

    const int row0 = blockIdx.x * ROWS_PER_CTA + warp * RPW;
    const float* xb = x + ((size_t)b * S_DIM + row0) * D_DIM + d0;
    const float* mb = mask + (size_t)b * S_DIM + row0;

    float l = 0.f;
    float acc[8];
#pragma unroll
    for (int i = 0; i < 8; i++) acc[i] = 0.f;

    // Prologue: load rows 0,1.
    float4 a0 = *reinterpret_cast<const float4*>(xb);
    float4 a1 = *reinterpret_cast<const float4*>(xb + 4);
    float4 c0 = *reinterpret_cast<const float4*>(xb + D_DIM);
    float4 c1 = *reinterpret_cast<const float4*>(xb + D_DIM + 4);
    float2 mk = *reinterpret_cast<const float2*>(mb);

#pragma unroll 1
    for (int r = 0; r < RPW; r += 2) {
        // ---- Prefetch next pair of rows BEFORE the reduce chain ----
        float4 na0, na1, nc0, nc1;
        float2 nmk;
        if (r + 2 < RPW) {
            const float* np = xb + (size_t)(r + 2) * D_DIM;
            na0 = *reinterpret_cast<const float4*>(np);
            na1 = *reinterpret_cast<const float4*>(np + 4);
            nc0 = *reinterpret_cast<const float4*>(np + D_DIM);
            nc1 = *reinterpret_cast<const float4*>(np + D_DIM + 4);
            nmk = *reinterpret_cast<const float2*>(mb + r + 2);
        }

        float xa[8] = {a0.x, a0.y, a0.z, a0.w, a1.x, a1.y, a1.z, a1.w};
        float xc[8] = {c0.x, c0.y, c0.z, c0.w, c1.x, c1.y, c1.z, c1.w};

        float sxA = 0.f, sxxA = 0.f, sdA = 0.f;
        float sxB = 0.f, sxxB = 0.f, sdB = 0.f;
#pragma unroll
        for (int i = 0; i < 8; i++) {
            sxA += xa[i];
            sxxA = fmaf(xa[i], xa[i], sxxA);
            sdA = fmaf(xa[i], gw[i], sdA);
            sxB += xc[i];
            sxxB = fmaf(xc[i], xc[i], sxxB);
            sdB = fmaf(xc[i], gw[i], sdB);
        }
        // Six interleaved warp reductions (independent chains).
#pragma unroll
        for (int off = 16; off > 0; off >>= 1) {
            sxA += __shfl_xor_sync(0xffffffffu, sxA, off);
            sxB += __shfl_xor_sync(0xffffffffu, sxB, off);
            sxxA += __shfl_xor_sync(0xffffffffu, sxxA, off);
            sxxB += __shfl_xor_sync(0xffffffffu, sxxB, off);
            sdA += __shfl_xor_sync(0xffffffffu, sdA, off);
            sdB += __shfl_xor_sync(0xffffffffu, sdB, off);
        }

        const float muA = sxA * (1.f / D_DIM);
        const float muB = sxB * (1.f / D_DIM);
        const float varA = sxxA * (1.f / D_DIM) - muA * muA;
        const float varB = sxxB * (1.f / D_DIM) - muB * muB;
        const float rsA = rsqrtf(varA + LN_EPS);
        const float rsB = rsqrtf(varB + LN_EPS);
        const float sA = rsA * (sdA - muA * GW) + BW + (1.f - mk.x) * -1e9f;
        const float sB = rsB * (sdB - muB * GW) + BW + (1.f - mk.y) * -1e9f;

        // Unnormalized accumulation (masked rows: exp(-1e9) -> 0).
        const float pA = __expf(sA);
        const float pB = __expf(sB);
        l += pA + pB;
#pragma unroll
        for (int i = 0; i < 8; i++)
            acc[i] = fmaf(pA, xa[i], fmaf(pB, xc[i], acc[i]));

        // Rotate double buffer.
        a0 = na0; a1 = na1; c0 = nc0; c1 = nc1; mk = nmk;
    }

    // Write partial state.
    const int ip = blockIdx.x * WPB + warp;  // 0..127 within batch
    const size_t pbase = (size_t)b * PARTIALS_PER_B + ip;
    if (lane == 0) g_l[pbase] = l;
    float* ab = g_acc + pbase * D_DIM + d0;
    *reinterpret_cast<float4*>(ab) = make_float4(acc[0], acc[1], acc[2], acc[3]);
    *reinterpret_cast<float4*>(ab + 4) = make_float4(acc[4], acc[5], acc[6], acc[7]);
}

// ---------------------------------------------------------------------------
// Pass 2: grid (B, SPLIT2). Plain linear reduction of an 8-partial chunk
// over all 256 dims (coalesced across threads).
// ---------------------------------------------------------------------------
__global__ __launch_bounds__(256) void attn_pool_pass2() {
    const int b = blockIdx.x;
    const int split = blockIdx.y;
    const int t = threadIdx.x;

    const size_t pb = (size_t)b * PARTIALS_PER_B + (size_t)split * CHUNK2;
    const float* ab = g_acc + pb * D_DIM + t;
    float o = 0.f;
#pragma unroll
    for (int i = 0; i < CHUNK2; i++)
        o += ab[(size_t)i * D_DIM];
    g_part[((size_t)split * B_DIM + b) * D_DIM + t] = o;
}

// ---------------------------------------------------------------------------
// Pass 3: sum SPLIT2 split-partials + divide by total l. 64 CTAs.
// ---------------------------------------------------------------------------
__global__ __launch_bounds__(256) void attn_pool_pass3(float* __restrict__ out) {
    const int b = blockIdx.x;
    const int t = threadIdx.x;
    const int lane = t & 31;

    __shared__ float Lsh;
    if (t < 32) {
        const float* lp = g_l + (size_t)b * PARTIALS_PER_B;
        float s = lp[lane] + lp[lane + 32] + lp[lane + 64] + lp[lane + 96];
#pragma unroll
        for (int off = 16; off > 0; off >>= 1)
            s += __shfl_xor_sync(0xffffffffu, s, off);
        if (lane == 0) Lsh = s;
    }
    __syncthreads();
    const float Linv = 1.f / Lsh;

    float o = 0.f;
#pragma unroll
    for (int s = 0; s < SPLIT2; s++)
        o += g_part[((size_t)s * B_DIM + b) * D_DIM + t];
    out[(size_t)b * D_DIM + t] = o * Linv;
}

extern "C" void kernel_launch(void* const* d_in, const int* in_sizes, int n_in,
                              void* d_out, int out_size) {
    const float* x = (const float*)d_in[0];      // [64,4096,256]
    const float* mask = (const float*)d_in[1];   // [64,4096]
    const float* gamma = (const float*)d_in[2];  // [256]
    const float* beta = (const float*)d_in[3];   // [256]
    const float* w = (const float*)d_in[4];      // [256]
    const float* bias = (const float*)d_in[5];   // scalar
    float* out = (float*)d_out;                  // [64,256]

    dim3 grid1(CTAS_PER_B, B_DIM);
    attn_pool_pass1<<<grid1, WPB * 32>>>(x, mask, gamma, beta, w, bias);
    dim3 grid2(B_DIM, SPLIT2);
    attn_pool_pass2<<<grid2, 256>>>();
    attn_pool_pass3<<<B_DIM, 256>>>(out);
}

// round 12
// speedup vs baseline: 1.2785x; 1.2432x over previous
#include <cuda_runtime.h>
#include <math.h>
#include <stdint.h>

// Problem constants
#define B_DIM 64
#define S_DIM 4096
#define D_DIM 256
#define LN_EPS 1e-3f

// Pass1 tiling: 8 warps/CTA, 64 rows/warp -> 512 rows per CTA
#define WPB 8
#define RPW 64
#define ROWS_PER_CTA (WPB * RPW)           // 512
#define CTAS_PER_B (S_DIM / ROWS_PER_CTA)  // 8
#define PARTIALS_PER_B (CTAS_PER_B * WPB)  // 64
#define ITERS (RPW / 2)                    // 32
#define STAGES 3

// Pass2 split
#define SPLIT2 8
#define CHUNK2 (PARTIALS_PER_B / SPLIT2)   // 8

// Scratch. No max-tracking (LN-bounded scores; exp cannot overflow) ->
// partials combine linearly.
__device__ float g_acc[B_DIM * PARTIALS_PER_B * D_DIM];   // 4 MB
__device__ float g_l[B_DIM * PARTIALS_PER_B];
__device__ float g_part[SPLIT2 * B_DIM * D_DIM];          // 512 KB

__device__ __forceinline__ float warp_sum(float v) {
#pragma unroll
    for (int off = 16; off > 0; off >>= 1)
        v += __shfl_xor_sync(0xffffffffu, v, off);
    return v;
}

__device__ __forceinline__ void cp16(void* s, const void* g) {
    uint32_t sa = (uint32_t)__cvta_generic_to_shared(s);
    asm volatile("cp.async.cg.shared.global [%0], [%1], 16;\n" ::"r"(sa), "l"(g));
}

// ---------------------------------------------------------------------------
// Pass 1: single pass over x. Per-warp 3-stage cp.async pipeline into smem:
// loads cost no registers and run 2 iterations ahead of the compute chain.
// Each lane writes/reads only its own 32 bytes (swizzled, conflict-free), so
// no block barrier is needed — cp.async.wait_group per thread suffices.
// ---------------------------------------------------------------------------
__global__ __launch_bounds__(256, 4) void attn_pool_pass1(
    const float* __restrict__ x, const float* __restrict__ mask,
    const float* __restrict__ gamma, const float* __restrict__ beta,
    const float* __restrict__ w, const float* __restrict__ bias_p) {
    __shared__ __align__(1024) char sbuf[WPB][STAGES][2048];

    const int b = blockIdx.y;
    const int warp = threadIdx.x >> 5;
    const int lane = threadIdx.x & 31;
    const int d0 = lane * 8;

    // Per-lane gamma*w; warp-uniform constants GW, BW.
    float gw[8];
    float gwsum = 0.f, bwsum = 0.f;
#pragma unroll
    for (int i = 0; i < 8; i++) {
        float wi = w[d0 + i];
        gw[i] = gamma[d0 + i] * wi;
        gwsum += gw[i];
        bwsum += beta[d0 + i] * wi;
    }
    const float GW = warp_sum(gwsum);
    const float BW = warp_sum(bwsum) + bias_p[0];

    const int row0 = blockIdx.x * ROWS_PER_CTA + warp * RPW;
    const char* xb = (const char*)(x + ((size_t)b * S_DIM + row0) * D_DIM);
    const float* mb = mask + (size_t)b * S_DIM + row0;

    // Preload this warp's 64 mask addends (2 per lane), broadcast later.
    const float madd0 = (1.f - mb[lane]) * -1e9f;
    const float madd1 = (1.f - mb[lane + 32]) * -1e9f;

    // Swizzled intra-chunk byte offsets for this lane (conflict-free).
    const int o0 = lane * 32;
    const int sw0 = o0 ^ ((o0 >> 3) & 0x70);
    const int o1 = o0 + 16;
    const int sw1 = o1 ^ ((o1 >> 3) & 0x70);

    char* const wbuf = sbuf[warp][0];

    // Issue iteration it's two rows into stage (it % STAGES).
    auto issue = [&](int it, int stage) {
        char* st = wbuf + stage * 2048;
        const char* g = xb + (size_t)it * 2048;
        cp16(st + sw0, g + o0);
        cp16(st + sw1, g + o1);
        cp16(st + 1024 + sw0, g + 1024 + o0);
        cp16(st + 1024 + sw1, g + 1024 + o1);
    };

    // Prologue: fill the pipeline.
    issue(0, 0); asm volatile("cp.async.commit_group;\n" ::: "memory");
    issue(1, 1); asm volatile("cp.async.commit_group;\n" ::: "memory");
    issue(2, 2); asm volatile("cp.async.commit_group;\n" ::: "memory");

    float l = 0.f;
    float acc[8];
#pragma unroll
    for (int i = 0; i < 8; i++) acc[i] = 0.f;

    int stage = 0;
#pragma unroll 1
    for (int it = 0; it < ITERS; ++it) {
        asm volatile("cp.async.wait_group 2;\n" ::: "memory");

        const char* st = wbuf + stage * 2048;
        const float4 a0 = *reinterpret_cast<const float4*>(st + sw0);
        const float4 a1 = *reinterpret_cast<const float4*>(st + sw1);
        const float4 c0 = *reinterpret_cast<const float4*>(st + 1024 + sw0);
        const float4 c1 = *reinterpret_cast<const float4*>(st + 1024 + sw1);
        float xa[8] = {a0.x, a0.y, a0.z, a0.w, a1.x, a1.y, a1.z, a1.w};
        float xc[8] = {c0.x, c0.y, c0.z, c0.w, c1.x, c1.y, c1.z, c1.w};

        float sxA = 0.f, sxxA = 0.f, sdA = 0.f;
        float sxB = 0.f, sxxB = 0.f, sdB = 0.f;
#pragma unroll
        for (int i = 0; i < 8; i++) {
            sxA += xa[i];
            sxxA = fmaf(xa[i], xa[i], sxxA);
            sdA = fmaf(xa[i], gw[i], sdA);
            sxB += xc[i];
            sxxB = fmaf(xc[i], xc[i], sxxB);
            sdB = fmaf(xc[i], gw[i], sdB);
        }
#pragma unroll
        for (int off = 16; off > 0; off >>= 1) {
            sxA += __shfl_xor_sync(0xffffffffu, sxA, off);
            sxB += __shfl_xor_sync(0xffffffffu, sxB, off);
            sxxA += __shfl_xor_sync(0xffffffffu, sxxA, off);
            sxxB += __shfl_xor_sync(0xffffffffu, sxxB, off);
            sdA += __shfl_xor_sync(0xffffffffu, sdA, off);
            sdB += __shfl_xor_sync(0xffffffffu, sdB, off);
        }

        // Mask addends for rows 2it, 2it+1 (same 32-block; warp-uniform sel).
        const int r2 = 2 * it;
        const float msrc = (r2 < 32) ? madd0 : madd1;
        const float mA = __shfl_sync(0xffffffffu, msrc, r2 & 31);
        const float mB = __shfl_sync(0xffffffffu, msrc, (r2 + 1) & 31);

        const float muA = sxA * (1.f / D_DIM);
        const float muB = sxB * (1.f / D_DIM);
        const float varA = sxxA * (1.f / D_DIM) - muA * muA;
        const float varB = sxxB * (1.f / D_DIM) - muB * muB;
        const float rsA = rsqrtf(varA + LN_EPS);
        const float rsB = rsqrtf(varB + LN_EPS);
        const float sA = rsA * (sdA - muA * GW) + BW + mA;
        const float sB = rsB * (sdB - muB * GW) + BW + mB;

        const float pA = __expf(sA);
        const float pB = __expf(sB);
        l += pA + pB;
#pragma unroll
        for (int i = 0; i < 8; i++)
            acc[i] = fmaf(pA, xa[i], fmaf(pB, xc[i], acc[i]));

        // Refill the stage we just consumed; always commit (keeps group<->iter
        // mapping so wait_group 2 always means "iter it's data has landed").
        if (it + STAGES < ITERS) issue(it + STAGES, stage);
        asm volatile("cp.async.commit_group;\n" ::: "memory");

        stage = (stage == STAGES - 1) ? 0 : stage + 1;
    }
    asm volatile("cp.async.wait_all;\n" ::: "memory");

    // Write partial state.
    const int ip = blockIdx.x * WPB + warp;  // 0..63 within batch
    const size_t pbase = (size_t)b * PARTIALS_PER_B + ip;
    if (lane == 0) g_l[pbase] = l;
    float* ab = g_acc + pbase * D_DIM + d0;
    *reinterpret_cast<float4*>(ab) = make_float4(acc[0], acc[1], acc[2], acc[3]);
    *reinterpret_cast<float4*>(ab + 4) = make_float4(acc[4], acc[5], acc[6], acc[7]);
}

// ---------------------------------------------------------------------------
// Pass 2: grid (B, SPLIT2). Linear reduction of an 8-partial chunk over all
// 256 dims (coalesced across threads).
// ---------------------------------------------------------------------------
__global__ __launch_bounds__(256) void attn_pool_pass2() {
    const int b = blockIdx.x;
    const int split = blockIdx.y;
    const int t = threadIdx.x;

    const size_t pb = (size_t)b * PARTIALS_PER_B + (size_t)split * CHUNK2;
    const float* ab = g_acc + pb * D_DIM + t;
    float o = 0.f;
#pragma unroll
    for (int i = 0; i < CHUNK2; i++)
        o += ab[(size_t)i * D_DIM];
    g_part[((size_t)split * B_DIM + b) * D_DIM + t] = o;
}

// ---------------------------------------------------------------------------
// Pass 3: sum SPLIT2 split-partials + divide by total l. 64 CTAs.
// ---------------------------------------------------------------------------
__global__ __launch_bounds__(256) void attn_pool_pass3(float* __restrict__ out) {
    const int b = blockIdx.x;
    const int t = threadIdx.x;
    const int lane = t & 31;

    __shared__ float Lsh;
    if (t < 32) {
        const float* lp = g_l + (size_t)b * PARTIALS_PER_B;
        float s = lp[lane] + lp[lane + 32];
#pragma unroll
        for (int off = 16; off > 0; off >>= 1)
            s += __shfl_xor_sync(0xffffffffu, s, off);
        if (lane == 0) Lsh = s;
    }
    __syncthreads();
    const float Linv = 1.f / Lsh;

    float o = 0.f;
#pragma unroll
    for (int s = 0; s < SPLIT2; s++)
        o += g_part[((size_t)s * B_DIM + b) * D_DIM + t];
    out[(size_t)b * D_DIM + t] = o * Linv;
}

extern "C" void kernel_launch(void* const* d_in, const int* in_sizes, int n_in,
                              void* d_out, int out_size) {
    const float* x = (const float*)d_in[0];      // [64,4096,256]
    const float* mask = (const float*)d_in[1];   // [64,4096]
    const float* gamma = (const float*)d_in[2];  // [256]
    const float* beta = (const float*)d_in[3];   // [256]
    const float* w = (const float*)d_in[4];      // [256]
    const float* bias = (const float*)d_in[5];   // scalar
    float* out = (float*)d_out;                  // [64,256]

    dim3 grid1(CTAS_PER_B, B_DIM);               // 8 x 64 = 512 CTAs -> 1 wave
    attn_pool_pass1<<<grid1, WPB * 32>>>(x, mask, gamma, beta, w, bias);
    dim3 grid2(B_DIM, SPLIT2);
    attn_pool_pass2<<<grid2, 256>>>();
    attn_pool_pass3<<<B_DIM, 256>>>(out);
}